// round 1
// baseline (speedup 1.0000x reference)
#include <cuda_runtime.h>
#include <stdint.h>

#define NCODE 1024
#define CDIM  256
#define NPIX  65536
#define HW    1024
#define BCHW  16777216

// Scratch (device globals: no allocations allowed in kernel_launch)
__device__ unsigned long long g_keys[NPIX];
__device__ float g_wsq[NCODE];
__device__ float g_xsq[NPIX];

// Order-preserving float->uint map, packed with index so that
// atomicMin picks (lowest score, then lowest index) == jnp.argmin semantics.
__device__ __forceinline__ unsigned long long packKey(float s, unsigned idx) {
    unsigned u = __float_as_uint(s);
    u = (u & 0x80000000u) ? ~u : (u | 0x80000000u);
    return (((unsigned long long)u) << 32) | (unsigned long long)idx;
}

__global__ void init_keys_kernel() {
    int i = blockIdx.x * blockDim.x + threadIdx.x;
    if (i < NPIX) g_keys[i] = 0xFFFFFFFFFFFFFFFFULL;
}

// |w|^2 per code (1024 blocks x 256 threads)
__global__ void wsq_kernel(const float* __restrict__ w) {
    __shared__ float red[8];
    int c = blockIdx.x;
    float v = w[c * CDIM + threadIdx.x];
    v = v * v;
    #pragma unroll
    for (int o = 16; o > 0; o >>= 1) v += __shfl_down_sync(0xffffffffu, v, o);
    if ((threadIdx.x & 31) == 0) red[threadIdx.x >> 5] = v;
    __syncthreads();
    if (threadIdx.x == 0) {
        float s = ((red[0] + red[1]) + (red[2] + red[3])) +
                  ((red[4] + red[5]) + (red[6] + red[7]));
        g_wsq[c] = s;
    }
}

// |x|^2 per pixel. Pixel p = (b, h, w) flat; x layout (B, C, H, W):
// element (p, c) lives at (p>>10)*CDIM*HW + c*HW + (p&1023).
__global__ void xsq_kernel(const float* __restrict__ x) {
    int p = blockIdx.x * blockDim.x + threadIdx.x;
    if (p >= NPIX) return;
    const float* base = x + (size_t)(p >> 10) * (CDIM * HW) + (p & 1023);
    float s0 = 0.f, s1 = 0.f, s2 = 0.f, s3 = 0.f;
    #pragma unroll 8
    for (int c = 0; c < CDIM; c += 4) {
        float v0 = base[(c + 0) * HW];
        float v1 = base[(c + 1) * HW];
        float v2 = base[(c + 2) * HW];
        float v3 = base[(c + 3) * HW];
        s0 += v0 * v0; s1 += v1 * v1; s2 += v2 * v2; s3 += v3 * v3;
    }
    g_xsq[p] = (s0 + s1) + (s2 + s3);
}

// Fused GEMM (128 pixels x 128 codes per block, K=256 in 16-chunks) + argmin.
// 256 threads, 8x8 register microtile each.
__global__ __launch_bounds__(256) void gemm_argmin_kernel(const float* __restrict__ x,
                                                          const float* __restrict__ w) {
    __shared__ float As[16][128];
    __shared__ float Bs[16][128];
    __shared__ unsigned long long red[128][16];

    const int tid  = threadIdx.x;
    const int tx   = tid & 15;     // code-tile coordinate
    const int ty   = tid >> 4;     // pixel-tile coordinate
    const int row0 = blockIdx.y * 128;   // pixel base
    const int col0 = blockIdx.x * 128;   // code base

    // 128-aligned pixel tiles never cross a batch boundary (1024 % 128 == 0)
    const float* xbase = x + (size_t)(row0 >> 10) * (CDIM * HW) + (row0 & 1023);

    // Loader mappings
    const int la_k = tid >> 5;          // 0..7   (two halves: +0, +8)
    const int la_m = (tid & 31) * 4;    // 0..124
    const int lb_n = tid >> 1;          // 0..127
    const int lb_k = (tid & 1) * 8;     // 0 or 8

    float acc[8][8];
    #pragma unroll
    for (int i = 0; i < 8; i++)
        #pragma unroll
        for (int j = 0; j < 8; j++) acc[i][j] = 0.f;

    for (int kt = 0; kt < CDIM; kt += 16) {
        // As[k][m] : 16 x 128, coalesced float4 from x (contiguous along pixels)
        #pragma unroll
        for (int h = 0; h < 2; h++) {
            int k = la_k + h * 8;
            float4 v = *(const float4*)(xbase + (size_t)(kt + k) * HW + la_m);
            *(float4*)&As[k][la_m] = v;
        }
        // Bs[k][n] : transpose-store from row-major weight
        {
            const float* wrow = w + (size_t)(col0 + lb_n) * CDIM + kt + lb_k;
            float4 v0 = *(const float4*)(wrow);
            float4 v1 = *(const float4*)(wrow + 4);
            Bs[lb_k + 0][lb_n] = v0.x; Bs[lb_k + 1][lb_n] = v0.y;
            Bs[lb_k + 2][lb_n] = v0.z; Bs[lb_k + 3][lb_n] = v0.w;
            Bs[lb_k + 4][lb_n] = v1.x; Bs[lb_k + 5][lb_n] = v1.y;
            Bs[lb_k + 6][lb_n] = v1.z; Bs[lb_k + 7][lb_n] = v1.w;
        }
        __syncthreads();

        #pragma unroll
        for (int k = 0; k < 16; k++) {
            float a[8], b[8];
            *(float4*)&a[0] = *(const float4*)&As[k][ty * 8];
            *(float4*)&a[4] = *(const float4*)&As[k][ty * 8 + 4];
            *(float4*)&b[0] = *(const float4*)&Bs[k][tx * 8];
            *(float4*)&b[4] = *(const float4*)&Bs[k][tx * 8 + 4];
            #pragma unroll
            for (int i = 0; i < 8; i++)
                #pragma unroll
                for (int j = 0; j < 8; j++)
                    acc[i][j] += a[i] * b[j];
        }
        __syncthreads();
    }

    // Epilogue: score = fl(fl(|x|^2 - 2*dot) + |w|^2), replicating the
    // reference's fp32 rounding pattern (separate mul/sub/add, no FMA fusion).
    float arow[8], wsq8[8];
    #pragma unroll
    for (int i = 0; i < 8; i++) arow[i] = g_xsq[row0 + ty * 8 + i];
    #pragma unroll
    for (int j = 0; j < 8; j++) wsq8[j] = g_wsq[col0 + tx * 8 + j];

    #pragma unroll
    for (int i = 0; i < 8; i++) {
        unsigned long long best = 0xFFFFFFFFFFFFFFFFULL;
        #pragma unroll
        for (int j = 0; j < 8; j++) {
            float m2 = __fmul_rn(2.0f, acc[i][j]);
            float t  = __fsub_rn(arow[i], m2);
            float s  = __fadd_rn(t, wsq8[j]);
            unsigned long long kk = packKey(s, (unsigned)(col0 + tx * 8 + j));
            best = (kk < best) ? kk : best;
        }
        red[ty * 8 + i][tx] = best;
    }
    __syncthreads();

    if (tid < 128) {
        unsigned long long b = red[tid][0];
        #pragma unroll
        for (int t = 1; t < 16; t++) {
            unsigned long long v = red[tid][t];
            b = (v < b) ? v : b;
        }
        atomicMin(&g_keys[row0 + tid], b);
    }
}

// Gather + write all three outputs. One block per (b, h) row of 32 pixels.
__global__ __launch_bounds__(256) void gather_kernel(const float* __restrict__ w,
                                                     float* __restrict__ out) {
    __shared__ float wsh[32][257];   // padded: conflict-free transposed reads
    __shared__ int idxsh[32];

    const int bh = blockIdx.x;       // 0..2047
    const int b  = bh >> 5;
    const int h  = bh & 31;
    const int p0 = bh * 32;
    const int tid = threadIdx.x;

    if (tid < 32) {
        unsigned long long key = g_keys[p0 + tid];
        int idx = (int)(key & 0xFFFFFFFFULL);
        idxsh[tid] = idx;
        out[2 * BCHW + p0 + tid] = (float)idx;   // idxs as float
    }
    __syncthreads();

    // Stage the 32 selected code rows (coalesced per row)
    for (int j = tid; j < 32 * CDIM; j += 256) {
        int wl = j >> 8, c = j & 255;
        wsh[wl][c] = w[(size_t)idxsh[wl] * CDIM + c];
    }
    __syncthreads();

    // quantized (B,C,H,W) + identical ste copy; fully coalesced writes
    const int qbase = b * (CDIM * HW) + h * 32;
    for (int j = tid; j < 32 * CDIM; j += 256) {
        int c = j >> 5, ww = j & 31;
        float v = wsh[ww][c];
        int addr = qbase + c * HW + ww;
        out[addr] = v;
        out[addr + BCHW] = v;
    }
}

extern "C" void kernel_launch(void* const* d_in, const int* in_sizes, int n_in,
                              void* d_out, int out_size) {
    const float* x = (const float*)d_in[0];   // (64, 256, 32, 32) f32
    const float* w = (const float*)d_in[1];   // (1024, 256) f32
    float* out = (float*)d_out;

    init_keys_kernel<<<NPIX / 256, 256>>>();
    wsq_kernel<<<NCODE, 256>>>(w);
    xsq_kernel<<<NPIX / 256, 256>>>(x);

    dim3 grid(NCODE / 128, NPIX / 128);       // (8, 512): pixel tile fast-varying in y
    gemm_argmin_kernel<<<grid, 256>>>(x, w);

    gather_kernel<<<NPIX / 32, 256>>>(w, out);
}

// round 5
// speedup vs baseline: 1.1327x; 1.1327x over previous
#include <cuda_runtime.h>
#include <cuda_bf16.h>
#include <stdint.h>

#define NCODE 1024
#define CDIM  256
#define NPIX  65536
#define HW    1024
#define BCHW  16777216
#define FLAG_CAP 16384
#define GAP_THRESH 2.0e-4f

// ---------------- device scratch (no allocations allowed) ----------------
__device__ __nv_bfloat16 g_xhi[(size_t)NPIX * CDIM];   // 32 MB
__device__ __nv_bfloat16 g_xlo[(size_t)NPIX * CDIM];   // 32 MB
__device__ __nv_bfloat16 g_whi[NCODE * CDIM];
__device__ __nv_bfloat16 g_wlo[NCODE * CDIM];
__device__ float g_wsq[NCODE];
__device__ float g_xsq[NPIX];
__device__ int   g_idx[NPIX];
__device__ int   g_flag_cnt;
__device__ int   g_flag_list[FLAG_CAP];

__device__ __forceinline__ uint32_t smem_u32(const void* p) {
    uint32_t a;
    asm("{ .reg .u64 t; cvta.to.shared.u64 t, %1; cvt.u32.u64 %0, t; }" : "=r"(a) : "l"(p));
    return a;
}

__device__ __forceinline__ unsigned long long packKey(float s, unsigned idx) {
    unsigned u = __float_as_uint(s);
    u = (u & 0x80000000u) ? ~u : (u | 0x80000000u);
    return (((unsigned long long)u) << 32) | (unsigned long long)idx;
}

__device__ __forceinline__ void cpasync16(uint32_t d, const void* s) {
    asm volatile("cp.async.ca.shared.global [%0], [%1], 16;" :: "r"(d), "l"(s) : "memory");
}

__device__ __forceinline__ void ldsm4(uint32_t* r, uint32_t addr) {
    asm volatile("ldmatrix.sync.aligned.m8n8.x4.shared.b16 {%0,%1,%2,%3}, [%4];"
                 : "=r"(r[0]), "=r"(r[1]), "=r"(r[2]), "=r"(r[3]) : "r"(addr));
}

__device__ __forceinline__ void mma_bf16(float* c, const uint32_t* a, const uint32_t* b) {
    asm volatile(
        "mma.sync.aligned.m16n8k16.row.col.f32.bf16.bf16.f32 "
        "{%0,%1,%2,%3}, {%4,%5,%6,%7}, {%8,%9}, {%0,%1,%2,%3};"
        : "+f"(c[0]), "+f"(c[1]), "+f"(c[2]), "+f"(c[3])
        : "r"(a[0]), "r"(a[1]), "r"(a[2]), "r"(a[3]), "r"(b[0]), "r"(b[1]));
}

// ---------------- prep kernels ----------------
__global__ void prep_w(const float* __restrict__ w) {
    __shared__ float red[8];
    int code = blockIdx.x, t = threadIdx.x;
    if (code == 0 && t == 0) g_flag_cnt = 0;   // reset per launch/replay
    float v = w[code * CDIM + t];
    __nv_bfloat16 hi = __float2bfloat16(v);
    g_whi[code * CDIM + t] = hi;
    g_wlo[code * CDIM + t] = __float2bfloat16(v - __bfloat162float(hi));
    float s = v * v;
    #pragma unroll
    for (int o = 16; o > 0; o >>= 1) s += __shfl_down_sync(0xffffffffu, s, o);
    if ((t & 31) == 0) red[t >> 5] = s;
    __syncthreads();
    if (t == 0) {
        g_wsq[code] = ((red[0] + red[1]) + (red[2] + red[3])) +
                      ((red[4] + red[5]) + (red[6] + red[7]));
    }
}

// x (B,C,H,W) f32 -> (pixel, C) bf16 hi/lo + |x|^2
__global__ void prep_x(const float* __restrict__ x) {
    int p = blockIdx.x * 256 + threadIdx.x;
    const float* base = x + (size_t)(p >> 10) * (CDIM * HW) + (p & 1023);
    float s0 = 0.f, s1 = 0.f, s2 = 0.f, s3 = 0.f;
    uint4* dhi = (uint4*)(g_xhi + (size_t)p * CDIM);
    uint4* dlo = (uint4*)(g_xlo + (size_t)p * CDIM);
    #pragma unroll 4
    for (int c = 0; c < CDIM; c += 8) {
        float v[8];
        #pragma unroll
        for (int i = 0; i < 8; i++) v[i] = base[(c + i) * HW];
        s0 += v[0] * v[0]; s1 += v[1] * v[1]; s2 += v[2] * v[2]; s3 += v[3] * v[3];
        s0 += v[4] * v[4]; s1 += v[5] * v[5]; s2 += v[6] * v[6]; s3 += v[7] * v[7];
        uint32_t hw_[4], lw_[4];
        #pragma unroll
        for (int i = 0; i < 4; i++) {
            __nv_bfloat16 h0 = __float2bfloat16(v[2 * i]);
            __nv_bfloat16 h1 = __float2bfloat16(v[2 * i + 1]);
            __nv_bfloat16 l0 = __float2bfloat16(v[2 * i]     - __bfloat162float(h0));
            __nv_bfloat16 l1 = __float2bfloat16(v[2 * i + 1] - __bfloat162float(h1));
            hw_[i] = (uint32_t)__bfloat16_as_ushort(h0) | ((uint32_t)__bfloat16_as_ushort(h1) << 16);
            lw_[i] = (uint32_t)__bfloat16_as_ushort(l0) | ((uint32_t)__bfloat16_as_ushort(l1) << 16);
        }
        dhi[c >> 3] = make_uint4(hw_[0], hw_[1], hw_[2], hw_[3]);
        dlo[c >> 3] = make_uint4(lw_[0], lw_[1], lw_[2], lw_[3]);
    }
    g_xsq[p] = (s0 + s1) + (s2 + s3);
}

// ---------------- fused HMMA GEMM + top-2 argmin ----------------
// smem: XHI 64KB | XLO 64KB | A double-buffer 2x16KB | reduction arrays 6KB
#define SM_XHI  0
#define SM_XLO  65536
#define SM_A    131072
#define SM_RED  163840
#define SM_TOT  (163840 + 6144)

// Stage one W k-slice: 128 codes x 64 bf16 (16KB), swizzled rows of 128B.
__device__ __forceinline__ void stage_slice(uint32_t sb, int g, int tid) {
    int ct = g >> 3, s = g & 7;
    const __nv_bfloat16* base = (s < 4) ? g_whi : g_wlo;
    const char* src = (const char*)(base + (size_t)(ct * 128) * CDIM + (s & 3) * 64);
    int r = tid >> 1, half = tid & 1;
    uint32_t dst = sb + SM_A + (uint32_t)(g & 1) * 16384 + r * 128;
    uint32_t xm = (r & 7) << 4;
    const char* srow = src + (size_t)r * 512;
    #pragma unroll
    for (int j = 0; j < 4; j++) {
        uint32_t kb = half * 64 + j * 16;
        cpasync16(dst + (kb ^ xm), srow + kb);
    }
}

__global__ __launch_bounds__(256, 1) void vq_mma() {
    extern __shared__ char smem[];
    uint32_t sb = smem_u32(smem);
    const int tid = threadIdx.x, l = tid & 31, wid = tid >> 5;
    const int mw = wid & 3, nw = wid >> 2;
    const int row0 = blockIdx.x * 128;
    // cross-warp top-2 merge arrays: [4 warps][128 pixels]
    float* s1sh = (float*)(smem + SM_RED);
    int*   i1sh = (int*)(smem + SM_RED + 2048);
    float* s2sh = (float*)(smem + SM_RED + 4096);

    // Stage resident X strip (hi+lo), group 0
    {
        int r = tid >> 1, half = tid & 1;
        const char* shi = (const char*)(g_xhi + (size_t)(row0 + r) * CDIM);
        const char* slo = (const char*)(g_xlo + (size_t)(row0 + r) * CDIM);
        uint32_t dhi = sb + SM_XHI + r * 512, dlo = sb + SM_XLO + r * 512;
        uint32_t xm = (r & 7) << 4;
        #pragma unroll
        for (int j = 0; j < 16; j++) {
            uint32_t kb = half * 256 + j * 16;
            uint32_t sw = kb ^ xm;
            cpasync16(dhi + sw, shi + kb);
            cpasync16(dlo + sw, slo + kb);
        }
    }
    asm volatile("cp.async.commit_group;" ::: "memory");
    stage_slice(sb, 0, tid);
    asm volatile("cp.async.commit_group;" ::: "memory");

    float xsqr[16];
    #pragma unroll
    for (int s = 0; s < 16; s++) {
        int px = nw * 64 + (s >> 1) * 8 + (l & 3) * 2 + (s & 1);
        xsqr[s] = g_xsq[row0 + px];
    }

    uint32_t a_row[2], a_x[2];
    #pragma unroll
    for (int tm = 0; tm < 2; tm++) {
        int rA = mw * 32 + tm * 16 + (l & 15);
        a_row[tm] = rA * 128;
        a_x[tm] = (rA & 7) << 4;
    }
    const uint32_t off16a = (l >> 4) * 16;
    uint32_t b_row[4], b_x[4];
    #pragma unroll
    for (int tp = 0; tp < 4; tp++) {
        int rB = nw * 64 + tp * 16 + (l & 7) + ((l >> 4) << 3);
        b_row[tp] = rB * 512;
        b_x[tp] = (rB & 7) << 4;
    }
    const uint32_t off16b = ((l >> 3) & 1) * 16;

    float acc[2][8][4];
    #pragma unroll
    for (int i = 0; i < 2; i++)
        #pragma unroll
        for (int j = 0; j < 8; j++)
            #pragma unroll
            for (int k = 0; k < 4; k++) acc[i][j][k] = 0.f;

    float best_s[16], sec_s[16];
    int best_i[16];
    #pragma unroll
    for (int s = 0; s < 16; s++) { best_s[s] = 3.4e38f; sec_s[s] = 3.4e38f; best_i[s] = 0; }

    for (int g = 0; g < 64; g++) {
        if (g + 1 < 64) {
            stage_slice(sb, g + 1, tid);
            asm volatile("cp.async.commit_group;" ::: "memory");
            asm volatile("cp.async.wait_group 1;" ::: "memory");
        } else {
            asm volatile("cp.async.wait_group 0;" ::: "memory");
        }
        __syncthreads();

        uint32_t bufb = sb + SM_A + (uint32_t)(g & 1) * 16384;
        uint32_t kbB0 = (uint32_t)(g & 3) * 128;
        bool dual = (g & 7) < 4;   // whi slices pair with both XHI and XLO

        #pragma unroll
        for (int kk = 0; kk < 4; kk++) {
            uint32_t a0[4], a1[4];
            ldsm4(a0, bufb + a_row[0] + ((kk * 32 + off16a) ^ a_x[0]));
            ldsm4(a1, bufb + a_row[1] + ((kk * 32 + off16a) ^ a_x[1]));
            uint32_t kb = kbB0 + kk * 32 + off16b;
            #pragma unroll
            for (int tp = 0; tp < 4; tp++) {
                uint32_t b[4];
                ldsm4(b, sb + SM_XHI + b_row[tp] + (kb ^ b_x[tp]));
                mma_bf16(acc[0][2 * tp],     a0, b);
                mma_bf16(acc[0][2 * tp + 1], a0, b + 2);
                mma_bf16(acc[1][2 * tp],     a1, b);
                mma_bf16(acc[1][2 * tp + 1], a1, b + 2);
            }
            if (dual) {
                #pragma unroll
                for (int tp = 0; tp < 4; tp++) {
                    uint32_t b[4];
                    ldsm4(b, sb + SM_XLO + b_row[tp] + (kb ^ b_x[tp]));
                    mma_bf16(acc[0][2 * tp],     a0, b);
                    mma_bf16(acc[0][2 * tp + 1], a0, b + 2);
                    mma_bf16(acc[1][2 * tp],     a1, b);
                    mma_bf16(acc[1][2 * tp + 1], a1, b + 2);
                }
            }
        }

        if ((g & 7) == 7) {   // chunk complete: fold into running top-2
            int ct = g >> 3;
            int cb = ct * 128 + mw * 32 + (l >> 2);
            float wq0 = __ldg(&g_wsq[cb]);
            float wq1 = __ldg(&g_wsq[cb + 8]);
            float wq2 = __ldg(&g_wsq[cb + 16]);
            float wq3 = __ldg(&g_wsq[cb + 24]);
            #pragma unroll
            for (int tm = 0; tm < 2; tm++) {
                float wlo_ = tm ? wq2 : wq0;
                float whi_ = tm ? wq3 : wq1;
                int c_lo = cb + tm * 16, c_hi = cb + tm * 16 + 8;
                #pragma unroll
                for (int tn = 0; tn < 8; tn++) {
                    #pragma unroll
                    for (int rg = 0; rg < 4; rg++) {
                        int slot = tn * 2 + (rg & 1);
                        float dot = acc[tm][tn][rg];
                        float wq = (rg >> 1) ? whi_ : wlo_;
                        int code = (rg >> 1) ? c_hi : c_lo;
                        // replicate reference rounding: fl(fl(xsq - 2 dot) + wsq)
                        float s = __fadd_rn(__fsub_rn(xsqr[slot],
                                                      __fmul_rn(2.0f, dot)), wq);
                        if (s < best_s[slot]) {
                            sec_s[slot] = best_s[slot];
                            best_s[slot] = s; best_i[slot] = code;
                        } else if (s < sec_s[slot]) {
                            sec_s[slot] = s;
                        }
                        acc[tm][tn][rg] = 0.f;
                    }
                }
            }
        }
        __syncthreads();
    }

    // Cross-lane top-2 merge (xor butterfly over the 8 lanes sharing a pixel)
    #pragma unroll
    for (int s = 0; s < 16; s++) {
        float bs = best_s[s], ss = sec_s[s];
        int bi = best_i[s];
        #pragma unroll
        for (int off = 4; off <= 16; off <<= 1) {
            float ob = __shfl_xor_sync(0xffffffffu, bs, off);
            int   oi = __shfl_xor_sync(0xffffffffu, bi, off);
            float os = __shfl_xor_sync(0xffffffffu, ss, off);
            bool take = (ob < bs) || (ob == bs && oi < bi);
            float losing = take ? bs : ob;
            if (take) { bs = ob; bi = oi; }
            ss = fminf(fminf(ss, os), losing);
        }
        if ((l >> 2) == 0) {
            int px = nw * 64 + (s >> 1) * 8 + (l & 3) * 2 + (s & 1);
            s1sh[mw * 128 + px] = bs;
            i1sh[mw * 128 + px] = bi;
            s2sh[mw * 128 + px] = ss;
        }
    }
    __syncthreads();

    // Cross-warp merge (4 warps per pixel), flag near-ties for exact rescue
    if (tid < 128) {
        float bs = s1sh[tid]; int bi = i1sh[tid]; float ss = s2sh[tid];
        #pragma unroll
        for (int wv = 1; wv < 4; wv++) {
            float ob = s1sh[wv * 128 + tid];
            int   oi = i1sh[wv * 128 + tid];
            float os = s2sh[wv * 128 + tid];
            bool take = (ob < bs) || (ob == bs && oi < bi);
            float losing = take ? bs : ob;
            if (take) { bs = ob; bi = oi; }
            ss = fminf(fminf(ss, os), losing);
        }
        g_idx[row0 + tid] = bi;
        if (ss - bs < GAP_THRESH) {
            int slot = atomicAdd(&g_flag_cnt, 1);
            if (slot < FLAG_CAP) g_flag_list[slot] = row0 + tid;
        }
    }
}

// ---------------- exact fp32 rescue for flagged pixels ----------------
__global__ __launch_bounds__(256) void rescue_kernel(const float* __restrict__ x,
                                                     const float* __restrict__ w) {
    __shared__ float xs[8][256];
    __shared__ float xsq_s[8];
    __shared__ unsigned long long best_sh[8];

    int nflag = g_flag_cnt;
    if (nflag > FLAG_CAP) nflag = FLAG_CAP;
    int ngroups = (nflag + 7) >> 3;
    const int tid = threadIdx.x;

    for (int grp = blockIdx.x; grp < ngroups; grp += gridDim.x) {
        int base = grp * 8;
        int npx = nflag - base; if (npx > 8) npx = 8;
        __syncthreads();
        for (int i = tid; i < npx * 256; i += 256) {
            int pi = i >> 8, c = i & 255;
            int p = g_flag_list[base + pi];
            xs[pi][c] = x[(size_t)(p >> 10) * (CDIM * HW) + c * HW + (p & 1023)];
        }
        if (tid < 8) {
            best_sh[tid] = ~0ull;
            if (tid < npx) xsq_s[tid] = g_xsq[g_flag_list[base + tid]];
        }
        __syncthreads();

        unsigned long long myb[8];
        #pragma unroll
        for (int p = 0; p < 8; p++) myb[p] = ~0ull;

        #pragma unroll
        for (int cc = 0; cc < 4; cc++) {
            int code = cc * 256 + tid;
            const float4* wrow = (const float4*)(w + (size_t)code * CDIM);
            float dots[8];
            #pragma unroll
            for (int p = 0; p < 8; p++) dots[p] = 0.f;
            #pragma unroll 8
            for (int k = 0; k < 256; k += 4) {
                float4 wv = wrow[k >> 2];
                #pragma unroll
                for (int p = 0; p < 8; p++) {
                    dots[p] = fmaf(wv.x, xs[p][k],     dots[p]);
                    dots[p] = fmaf(wv.y, xs[p][k + 1], dots[p]);
                    dots[p] = fmaf(wv.z, xs[p][k + 2], dots[p]);
                    dots[p] = fmaf(wv.w, xs[p][k + 3], dots[p]);
                }
            }
            float wq = __ldg(&g_wsq[code]);
            #pragma unroll
            for (int p = 0; p < 8; p++) {
                float s = __fadd_rn(__fsub_rn(xsq_s[p],
                                              __fmul_rn(2.0f, dots[p])), wq);
                unsigned long long k2 = packKey(s, (unsigned)code);
                if (k2 < myb[p]) myb[p] = k2;
            }
        }
        #pragma unroll
        for (int p = 0; p < 8; p++) atomicMin(&best_sh[p], myb[p]);
        __syncthreads();
        if (tid < npx)
            g_idx[g_flag_list[base + tid]] = (int)(best_sh[tid] & 0xFFFFFFFFULL);
    }
}

// ---------------- gather + write outputs ----------------
__global__ __launch_bounds__(256) void gather_kernel(const float* __restrict__ w,
                                                     float* __restrict__ out) {
    __shared__ float wsh[32][257];
    __shared__ int idxsh[32];

    const int bh = blockIdx.x;
    const int b  = bh >> 5;
    const int h  = bh & 31;
    const int p0 = bh * 32;
    const int tid = threadIdx.x;

    if (tid < 32) {
        int idx = g_idx[p0 + tid];
        idxsh[tid] = idx;
        out[2 * BCHW + p0 + tid] = (float)idx;
    }
    __syncthreads();

    for (int j = tid; j < 32 * CDIM; j += 256) {
        int wl = j >> 8, c = j & 255;
        wsh[wl][c] = w[(size_t)idxsh[wl] * CDIM + c];
    }
    __syncthreads();

    const int qbase = b * (CDIM * HW) + h * 32;
    for (int j = tid; j < 32 * CDIM; j += 256) {
        int c = j >> 5, ww = j & 31;
        float v = wsh[ww][c];
        int addr = qbase + c * HW + ww;
        out[addr] = v;
        out[addr + BCHW] = v;
    }
}

extern "C" void kernel_launch(void* const* d_in, const int* in_sizes, int n_in,
                              void* d_out, int out_size) {
    const float* x = (const float*)d_in[0];   // (64, 256, 32, 32) f32
    const float* w = (const float*)d_in[1];   // (1024, 256) f32
    float* out = (float*)d_out;

    cudaFuncSetAttribute(vq_mma, cudaFuncAttributeMaxDynamicSharedMemorySize, SM_TOT);

    prep_w<<<NCODE, 256>>>(w);
    prep_x<<<NPIX / 256, 256>>>(x);
    vq_mma<<<512, 256, SM_TOT>>>();
    rescue_kernel<<<256, 256>>>(x, w);
    gather_kernel<<<NPIX / 32, 256>>>(w, out);
}

// round 6
// speedup vs baseline: 1.3973x; 1.2336x over previous
#include <cuda_runtime.h>
#include <cuda_bf16.h>
#include <stdint.h>

#define NCODE 1024
#define CDIM  256
#define NPIX  65536
#define HW    1024
#define BCHW  16777216
#define FLAG_CAP 32768
#define GAP_THRESH 6.0e-4f

// ---------------- device scratch (no allocations allowed) ----------------
__device__ __nv_bfloat16 g_xhi[(size_t)NPIX * CDIM];   // 32 MB
__device__ __nv_bfloat16 g_whi[NCODE * CDIM];
__device__ float g_wsq[NCODE];
__device__ float g_xsq[NPIX];
__device__ int   g_idx[NPIX];
__device__ int   g_flag_cnt;
__device__ int   g_flag_list[FLAG_CAP];

__device__ __forceinline__ uint32_t smem_u32(const void* p) {
    uint32_t a;
    asm("{ .reg .u64 t; cvta.to.shared.u64 t, %1; cvt.u32.u64 %0, t; }" : "=r"(a) : "l"(p));
    return a;
}

__device__ __forceinline__ unsigned long long packKey(float s, unsigned idx) {
    unsigned u = __float_as_uint(s);
    u = (u & 0x80000000u) ? ~u : (u | 0x80000000u);
    return (((unsigned long long)u) << 32) | (unsigned long long)idx;
}

__device__ __forceinline__ void cpasync16(uint32_t d, const void* s) {
    asm volatile("cp.async.ca.shared.global [%0], [%1], 16;" :: "r"(d), "l"(s) : "memory");
}

__device__ __forceinline__ void ldsm4(uint32_t* r, uint32_t addr) {
    asm volatile("ldmatrix.sync.aligned.m8n8.x4.shared.b16 {%0,%1,%2,%3}, [%4];"
                 : "=r"(r[0]), "=r"(r[1]), "=r"(r[2]), "=r"(r[3]) : "r"(addr));
}

__device__ __forceinline__ void mma_bf16(float* c, const uint32_t* a, const uint32_t* b) {
    asm volatile(
        "mma.sync.aligned.m16n8k16.row.col.f32.bf16.bf16.f32 "
        "{%0,%1,%2,%3}, {%4,%5,%6,%7}, {%8,%9}, {%0,%1,%2,%3};"
        : "+f"(c[0]), "+f"(c[1]), "+f"(c[2]), "+f"(c[3])
        : "r"(a[0]), "r"(a[1]), "r"(a[2]), "r"(a[3]), "r"(b[0]), "r"(b[1]));
}

// ---------------- prep kernels ----------------
__global__ void prep_w(const float* __restrict__ w) {
    __shared__ float red[8];
    int code = blockIdx.x, t = threadIdx.x;
    if (code == 0 && t == 0) g_flag_cnt = 0;   // reset per launch/replay
    float v = w[code * CDIM + t];
    g_whi[code * CDIM + t] = __float2bfloat16(v);
    float s = v * v;
    #pragma unroll
    for (int o = 16; o > 0; o >>= 1) s += __shfl_down_sync(0xffffffffu, s, o);
    if ((t & 31) == 0) red[t >> 5] = s;
    __syncthreads();
    if (t == 0) {
        g_wsq[code] = ((red[0] + red[1]) + (red[2] + red[3])) +
                      ((red[4] + red[5]) + (red[6] + red[7]));
    }
}

// x (B,C,H,W) f32 -> (pixel, C) bf16 + |x|^2 (identical xsq arithmetic to R1/R5)
__global__ void prep_x(const float* __restrict__ x) {
    int p = blockIdx.x * 256 + threadIdx.x;
    const float* base = x + (size_t)(p >> 10) * (CDIM * HW) + (p & 1023);
    float s0 = 0.f, s1 = 0.f, s2 = 0.f, s3 = 0.f;
    uint4* dhi = (uint4*)(g_xhi + (size_t)p * CDIM);
    #pragma unroll 4
    for (int c = 0; c < CDIM; c += 8) {
        float v[8];
        #pragma unroll
        for (int i = 0; i < 8; i++) v[i] = base[(c + i) * HW];
        s0 += v[0] * v[0]; s1 += v[1] * v[1]; s2 += v[2] * v[2]; s3 += v[3] * v[3];
        s0 += v[4] * v[4]; s1 += v[5] * v[5]; s2 += v[6] * v[6]; s3 += v[7] * v[7];
        uint32_t hw_[4];
        #pragma unroll
        for (int i = 0; i < 4; i++) {
            __nv_bfloat16 h0 = __float2bfloat16(v[2 * i]);
            __nv_bfloat16 h1 = __float2bfloat16(v[2 * i + 1]);
            hw_[i] = (uint32_t)__bfloat16_as_ushort(h0) | ((uint32_t)__bfloat16_as_ushort(h1) << 16);
        }
        dhi[c >> 3] = make_uint4(hw_[0], hw_[1], hw_[2], hw_[3]);
    }
    g_xsq[p] = (s0 + s1) + (s2 + s3);
}

// ---------------- fused HMMA GEMM (single bf16 pass) + top-2 argmin ----------------
// smem: X 64KB | W double-buffer 2x64KB | reduction arrays 6KB
#define SM_X   0
#define SM_W   65536
#define SM_RED 196608
#define SM_TOT (196608 + 6144)

// Stage one full W tile: 128 codes x 256 bf16 (64KB), 512B swizzled rows.
__device__ __forceinline__ void stage_wtile(uint32_t sb, int ct, int tid) {
    int r = tid >> 1, half = tid & 1;
    uint32_t dst = sb + SM_W + (uint32_t)(ct & 1) * 65536 + (uint32_t)r * 512;
    uint32_t xm = (r & 7) << 4;
    const char* srow = (const char*)(g_whi + (size_t)(ct * 128 + r) * CDIM);
    #pragma unroll
    for (int j = 0; j < 16; j++) {
        uint32_t kb = half * 256 + j * 16;
        cpasync16(dst + (kb ^ xm), srow + kb);
    }
}

__global__ __launch_bounds__(256, 1) void vq_mma() {
    extern __shared__ char smem[];
    uint32_t sb = smem_u32(smem);
    const int tid = threadIdx.x, l = tid & 31, wid = tid >> 5;
    const int mw = wid & 3, nw = wid >> 2;
    const int row0 = blockIdx.x * 128;
    float* s1sh = (float*)(smem + SM_RED);
    int*   i1sh = (int*)(smem + SM_RED + 2048);
    float* s2sh = (float*)(smem + SM_RED + 4096);

    // Stage resident X strip (512B rows, swizzled) + W tile 0 as one group
    {
        int r = tid >> 1, half = tid & 1;
        const char* shi = (const char*)(g_xhi + (size_t)(row0 + r) * CDIM);
        uint32_t dx = sb + SM_X + (uint32_t)r * 512;
        uint32_t xm = (r & 7) << 4;
        #pragma unroll
        for (int j = 0; j < 16; j++) {
            uint32_t kb = half * 256 + j * 16;
            cpasync16(dx + (kb ^ xm), shi + kb);
        }
    }
    stage_wtile(sb, 0, tid);
    asm volatile("cp.async.commit_group;" ::: "memory");
    stage_wtile(sb, 1, tid);
    asm volatile("cp.async.commit_group;" ::: "memory");

    float xsqr[16];
    #pragma unroll
    for (int s = 0; s < 16; s++) {
        int px = nw * 64 + (s >> 1) * 8 + (l & 3) * 2 + (s & 1);
        xsqr[s] = g_xsq[row0 + px];
    }

    uint32_t a_row[2], a_x[2];
    #pragma unroll
    for (int tm = 0; tm < 2; tm++) {
        int rA = mw * 32 + tm * 16 + (l & 15);
        a_row[tm] = rA * 512;
        a_x[tm] = (rA & 7) << 4;
    }
    const uint32_t off16a = (l >> 4) * 16;
    uint32_t b_row[4], b_x[4];
    #pragma unroll
    for (int tp = 0; tp < 4; tp++) {
        int rB = nw * 64 + tp * 16 + (l & 7) + ((l >> 4) << 3);
        b_row[tp] = rB * 512;
        b_x[tp] = (rB & 7) << 4;
    }
    const uint32_t off16b = ((l >> 3) & 1) * 16;

    float acc[2][8][4];
    #pragma unroll
    for (int i = 0; i < 2; i++)
        #pragma unroll
        for (int j = 0; j < 8; j++)
            #pragma unroll
            for (int k = 0; k < 4; k++) acc[i][j][k] = 0.f;

    float best_s[16], sec_s[16];
    int best_i[16];
    #pragma unroll
    for (int s = 0; s < 16; s++) { best_s[s] = 3.4e38f; sec_s[s] = 3.4e38f; best_i[s] = 0; }

    for (int ct = 0; ct < 8; ct++) {
        if (ct < 7) asm volatile("cp.async.wait_group 1;" ::: "memory");
        else        asm volatile("cp.async.wait_group 0;" ::: "memory");
        __syncthreads();

        uint32_t bufw = sb + SM_W + (uint32_t)(ct & 1) * 65536;
        #pragma unroll 4
        for (int kk = 0; kk < 16; kk++) {
            uint32_t a0[4], a1[4];
            uint32_t ca = kk * 32 + off16a;
            ldsm4(a0, bufw + a_row[0] + (ca ^ a_x[0]));
            ldsm4(a1, bufw + a_row[1] + (ca ^ a_x[1]));
            uint32_t kb = kk * 32 + off16b;
            #pragma unroll
            for (int tp = 0; tp < 4; tp++) {
                uint32_t b[4];
                ldsm4(b, sb + SM_X + b_row[tp] + (kb ^ b_x[tp]));
                mma_bf16(acc[0][2 * tp],     a0, b);
                mma_bf16(acc[0][2 * tp + 1], a0, b + 2);
                mma_bf16(acc[1][2 * tp],     a1, b);
                mma_bf16(acc[1][2 * tp + 1], a1, b + 2);
            }
        }
        __syncthreads();   // all warps done reading bufw before restage
        if (ct + 2 < 8) {
            stage_wtile(sb, ct + 2, tid);
            asm volatile("cp.async.commit_group;" ::: "memory");
        }

        // Fold this code tile into running top-2 (overlaps the async restage)
        {
            int cb = ct * 128 + mw * 32 + (l >> 2);
            float wq0 = __ldg(&g_wsq[cb]);
            float wq1 = __ldg(&g_wsq[cb + 8]);
            float wq2 = __ldg(&g_wsq[cb + 16]);
            float wq3 = __ldg(&g_wsq[cb + 24]);
            #pragma unroll
            for (int tm = 0; tm < 2; tm++) {
                float wlo_ = tm ? wq2 : wq0;
                float whi_ = tm ? wq3 : wq1;
                int c_lo = cb + tm * 16, c_hi = cb + tm * 16 + 8;
                #pragma unroll
                for (int tn = 0; tn < 8; tn++) {
                    #pragma unroll
                    for (int rg = 0; rg < 4; rg++) {
                        int slot = tn * 2 + (rg & 1);
                        float dot = acc[tm][tn][rg];
                        float wq = (rg >> 1) ? whi_ : wlo_;
                        int code = (rg >> 1) ? c_hi : c_lo;
                        float s = __fadd_rn(__fsub_rn(xsqr[slot],
                                                      __fmul_rn(2.0f, dot)), wq);
                        if (s < best_s[slot]) {
                            sec_s[slot] = best_s[slot];
                            best_s[slot] = s; best_i[slot] = code;
                        } else if (s < sec_s[slot]) {
                            sec_s[slot] = s;
                        }
                        acc[tm][tn][rg] = 0.f;
                    }
                }
            }
        }
    }

    // Cross-lane top-2 merge
    #pragma unroll
    for (int s = 0; s < 16; s++) {
        float bs = best_s[s], ss = sec_s[s];
        int bi = best_i[s];
        #pragma unroll
        for (int off = 4; off <= 16; off <<= 1) {
            float ob = __shfl_xor_sync(0xffffffffu, bs, off);
            int   oi = __shfl_xor_sync(0xffffffffu, bi, off);
            float os = __shfl_xor_sync(0xffffffffu, ss, off);
            bool take = (ob < bs) || (ob == bs && oi < bi);
            float losing = take ? bs : ob;
            if (take) { bs = ob; bi = oi; }
            ss = fminf(fminf(ss, os), losing);
        }
        if ((l >> 2) == 0) {
            int px = nw * 64 + (s >> 1) * 8 + (l & 3) * 2 + (s & 1);
            s1sh[mw * 128 + px] = bs;
            i1sh[mw * 128 + px] = bi;
            s2sh[mw * 128 + px] = ss;
        }
    }
    __syncthreads();

    // Cross-warp merge; flag near-ties for exact rescue
    if (tid < 128) {
        float bs = s1sh[tid]; int bi = i1sh[tid]; float ss = s2sh[tid];
        #pragma unroll
        for (int wv = 1; wv < 4; wv++) {
            float ob = s1sh[wv * 128 + tid];
            int   oi = i1sh[wv * 128 + tid];
            float os = s2sh[wv * 128 + tid];
            bool take = (ob < bs) || (ob == bs && oi < bi);
            float losing = take ? bs : ob;
            if (take) { bs = ob; bi = oi; }
            ss = fminf(fminf(ss, os), losing);
        }
        g_idx[row0 + tid] = bi;
        if (ss - bs < GAP_THRESH) {
            int slot = atomicAdd(&g_flag_cnt, 1);
            if (slot < FLAG_CAP) g_flag_list[slot] = row0 + tid;
        }
    }
}

// ---------------- exact fp32 rescue (smem-staged W, 4x4 register tiles) ----------------
#define RPX 16
#define R_WPITCH 68    // floats per W smem row (64 + 4 pad) -> 272B
#define R_XPITCH 260   // floats per xs row (256 + 4 pad; [256] stores xsq)
#define RS_W    16640                 // after xs[16][260] f32
#define RS_WSZ  69632                 // 256 rows * 272B
#define RS_BEST (RS_W + 2 * RS_WSZ)   // 155904
#define RS_TOT  (RS_BEST + 256)

// Stage W slice s = ctile*4 + ks: 256 codes x 64 fp32
__device__ __forceinline__ void r_stage(uint32_t sb, const float* w, int s, int tid) {
    int ctile = s >> 2, ks = s & 3;
    const char* src = (const char*)(w + (size_t)(ctile * 256 + tid) * CDIM + ks * 64);
    uint32_t dst = sb + RS_W + (uint32_t)(s & 1) * RS_WSZ + (uint32_t)tid * (R_WPITCH * 4);
    #pragma unroll
    for (int j = 0; j < 16; j++) cpasync16(dst + j * 16, src + j * 16);
}

__global__ __launch_bounds__(256) void rescue_kernel(const float* __restrict__ x,
                                                     const float* __restrict__ w) {
    extern __shared__ char rsm[];
    uint32_t sb = smem_u32(rsm);
    float* xs = (float*)rsm;
    unsigned long long* best_sh = (unsigned long long*)(rsm + RS_BEST);
    const int tid = threadIdx.x;
    const int cq = tid >> 2, pq = tid & 3;   // code-quad, pixel-quad id

    int nflag = g_flag_cnt;
    if (nflag > FLAG_CAP) nflag = FLAG_CAP;
    int ngroups = (nflag + RPX - 1) / RPX;

    for (int grp = blockIdx.x; grp < ngroups; grp += gridDim.x) {
        int base = grp * RPX;
        __syncthreads();   // protect smem reuse across group iterations
        for (int i = tid; i < RPX * 256; i += 256) {
            int pi = i >> 8, c = i & 255;
            int fp = base + pi;
            int p = g_flag_list[(fp < nflag) ? fp : 0];
            xs[pi * R_XPITCH + c] = x[(size_t)(p >> 10) * (CDIM * HW) + c * HW + (p & 1023)];
        }
        if (tid < RPX) {
            int fp = base + tid;
            xs[tid * R_XPITCH + 256] = g_xsq[g_flag_list[(fp < nflag) ? fp : 0]];
            best_sh[tid] = ~0ull;
        }
        r_stage(sb, w, 0, tid);
        asm volatile("cp.async.commit_group;" ::: "memory");
        r_stage(sb, w, 1, tid);
        asm volatile("cp.async.commit_group;" ::: "memory");

        unsigned long long myb[4];
        float dots[4][4];
        #pragma unroll
        for (int j = 0; j < 4; j++) {
            myb[j] = ~0ull;
            #pragma unroll
            for (int i = 0; i < 4; i++) dots[i][j] = 0.f;
        }

        for (int s = 0; s < 16; s++) {
            if (s < 15) asm volatile("cp.async.wait_group 1;" ::: "memory");
            else        asm volatile("cp.async.wait_group 0;" ::: "memory");
            __syncthreads();
            const float* wb = (const float*)(rsm + RS_W + (size_t)(s & 1) * RS_WSZ);
            int kbase = (s & 3) * 64;
            #pragma unroll 4
            for (int k4 = 0; k4 < 16; k4++) {
                float4 wv[4], xv[4];
                #pragma unroll
                for (int i = 0; i < 4; i++)
                    wv[i] = *(const float4*)&wb[(cq + i * 64) * R_WPITCH + k4 * 4];
                #pragma unroll
                for (int j = 0; j < 4; j++)
                    xv[j] = *(const float4*)&xs[(pq + j * 4) * R_XPITCH + kbase + k4 * 4];
                #pragma unroll
                for (int i = 0; i < 4; i++)
                    #pragma unroll
                    for (int j = 0; j < 4; j++) {
                        float d = dots[i][j];
                        d = fmaf(wv[i].x, xv[j].x, d);
                        d = fmaf(wv[i].y, xv[j].y, d);
                        d = fmaf(wv[i].z, xv[j].z, d);
                        d = fmaf(wv[i].w, xv[j].w, d);
                        dots[i][j] = d;
                    }
            }
            __syncthreads();   // all done reading this buffer
            if (s + 2 < 16) {
                r_stage(sb, w, s + 2, tid);
                asm volatile("cp.async.commit_group;" ::: "memory");
            }
            if ((s & 3) == 3) {   // code tile complete: score + fold
                int ctile = s >> 2;
                #pragma unroll
                for (int i = 0; i < 4; i++) {
                    int code = ctile * 256 + cq + i * 64;
                    float wq = __ldg(&g_wsq[code]);
                    #pragma unroll
                    for (int j = 0; j < 4; j++) {
                        float xq = xs[(pq + j * 4) * R_XPITCH + 256];
                        float sc = __fadd_rn(__fsub_rn(xq,
                                     __fmul_rn(2.0f, dots[i][j])), wq);
                        unsigned long long k2 = packKey(sc, (unsigned)code);
                        if (k2 < myb[j]) myb[j] = k2;
                        dots[i][j] = 0.f;
                    }
                }
            }
        }
        #pragma unroll
        for (int j = 0; j < 4; j++) atomicMin(&best_sh[pq + j * 4], myb[j]);
        __syncthreads();
        if (tid < RPX && base + tid < nflag)
            g_idx[g_flag_list[base + tid]] = (int)(best_sh[tid] & 0xFFFFFFFFULL);
    }
}

// ---------------- gather + write outputs ----------------
__global__ __launch_bounds__(256) void gather_kernel(const float* __restrict__ w,
                                                     float* __restrict__ out) {
    __shared__ float wsh[32][257];
    __shared__ int idxsh[32];

    const int bh = blockIdx.x;
    const int b  = bh >> 5;
    const int h  = bh & 31;
    const int p0 = bh * 32;
    const int tid = threadIdx.x;

    if (tid < 32) {
        int idx = g_idx[p0 + tid];
        idxsh[tid] = idx;
        out[2 * BCHW + p0 + tid] = (float)idx;
    }
    __syncthreads();

    for (int j = tid; j < 32 * CDIM; j += 256) {
        int wl = j >> 8, c = j & 255;
        wsh[wl][c] = w[(size_t)idxsh[wl] * CDIM + c];
    }
    __syncthreads();

    const int qbase = b * (CDIM * HW) + h * 32;
    for (int j = tid; j < 32 * CDIM; j += 256) {
        int c = j >> 5, ww = j & 31;
        float v = wsh[ww][c];
        int addr = qbase + c * HW + ww;
        out[addr] = v;
        out[addr + BCHW] = v;
    }
}

extern "C" void kernel_launch(void* const* d_in, const int* in_sizes, int n_in,
                              void* d_out, int out_size) {
    const float* x = (const float*)d_in[0];   // (64, 256, 32, 32) f32
    const float* w = (const float*)d_in[1];   // (1024, 256) f32
    float* out = (float*)d_out;

    cudaFuncSetAttribute(vq_mma, cudaFuncAttributeMaxDynamicSharedMemorySize, SM_TOT);
    cudaFuncSetAttribute(rescue_kernel, cudaFuncAttributeMaxDynamicSharedMemorySize, RS_TOT);

    prep_w<<<NCODE, 256>>>(w);
    prep_x<<<NPIX / 256, 256>>>(x);
    vq_mma<<<512, 256, SM_TOT>>>();
    rescue_kernel<<<512, 256, RS_TOT>>>(x, w);
    gather_kernel<<<NPIX / 32, 256>>>(w, out);
}

// round 7
// speedup vs baseline: 1.9419x; 1.3898x over previous
#include <cuda_runtime.h>
#include <cuda_bf16.h>
#include <stdint.h>

#define NCODE 1024
#define CDIM  256
#define NPIX  65536
#define HW    1024
#define BCHW  16777216
#define FLAG_CAP 32768
#define CAND_CAP 131072
#define GAP_THRESH 6.0e-4f

// ---------------- device scratch (no allocations allowed) ----------------
__device__ __nv_bfloat16 g_xhi[(size_t)NPIX * CDIM];   // 32 MB
__device__ __nv_bfloat16 g_whi[NCODE * CDIM];
__device__ float g_wsq[NCODE];
__device__ float g_xsq[NPIX];
__device__ float g_bests[NPIX];
__device__ int   g_idx[NPIX];
__device__ unsigned long long g_key[NPIX];
__device__ int   g_flag_cnt;
__device__ int   g_flag_list[FLAG_CAP];
__device__ int   g_cand_cnt;
__device__ unsigned g_cand[CAND_CAP];

__device__ __forceinline__ uint32_t smem_u32(const void* p) {
    uint32_t a;
    asm("{ .reg .u64 t; cvta.to.shared.u64 t, %1; cvt.u32.u64 %0, t; }" : "=r"(a) : "l"(p));
    return a;
}

__device__ __forceinline__ unsigned long long packKey(float s, unsigned idx) {
    unsigned u = __float_as_uint(s);
    u = (u & 0x80000000u) ? ~u : (u | 0x80000000u);
    return (((unsigned long long)u) << 32) | (unsigned long long)idx;
}

__device__ __forceinline__ void cpasync16(uint32_t d, const void* s) {
    asm volatile("cp.async.ca.shared.global [%0], [%1], 16;" :: "r"(d), "l"(s) : "memory");
}

__device__ __forceinline__ void ldsm4(uint32_t* r, uint32_t addr) {
    asm volatile("ldmatrix.sync.aligned.m8n8.x4.shared.b16 {%0,%1,%2,%3}, [%4];"
                 : "=r"(r[0]), "=r"(r[1]), "=r"(r[2]), "=r"(r[3]) : "r"(addr));
}

__device__ __forceinline__ void mma_bf16(float* c, const uint32_t* a, const uint32_t* b) {
    asm volatile(
        "mma.sync.aligned.m16n8k16.row.col.f32.bf16.bf16.f32 "
        "{%0,%1,%2,%3}, {%4,%5,%6,%7}, {%8,%9}, {%0,%1,%2,%3};"
        : "+f"(c[0]), "+f"(c[1]), "+f"(c[2]), "+f"(c[3])
        : "r"(a[0]), "r"(a[1]), "r"(a[2]), "r"(a[3]), "r"(b[0]), "r"(b[1]));
}

// ---------------- prep kernels ----------------
__global__ void prep_w(const float* __restrict__ w) {
    __shared__ float red[8];
    int code = blockIdx.x, t = threadIdx.x;
    if (code == 0 && t == 0) { g_flag_cnt = 0; g_cand_cnt = 0; }
    float v = w[code * CDIM + t];
    g_whi[code * CDIM + t] = __float2bfloat16(v);
    float s = v * v;
    #pragma unroll
    for (int o = 16; o > 0; o >>= 1) s += __shfl_down_sync(0xffffffffu, s, o);
    if ((t & 31) == 0) red[t >> 5] = s;
    __syncthreads();
    if (t == 0) {
        g_wsq[code] = ((red[0] + red[1]) + (red[2] + red[3])) +
                      ((red[4] + red[5]) + (red[6] + red[7]));
    }
}

// x (B,C,H,W) f32 -> (pixel, C) bf16 + |x|^2
__global__ void prep_x(const float* __restrict__ x) {
    int p = blockIdx.x * 256 + threadIdx.x;
    const float* base = x + (size_t)(p >> 10) * (CDIM * HW) + (p & 1023);
    float s0 = 0.f, s1 = 0.f, s2 = 0.f, s3 = 0.f;
    uint4* dhi = (uint4*)(g_xhi + (size_t)p * CDIM);
    #pragma unroll 4
    for (int c = 0; c < CDIM; c += 8) {
        float v[8];
        #pragma unroll
        for (int i = 0; i < 8; i++) v[i] = base[(c + i) * HW];
        s0 += v[0] * v[0]; s1 += v[1] * v[1]; s2 += v[2] * v[2]; s3 += v[3] * v[3];
        s0 += v[4] * v[4]; s1 += v[5] * v[5]; s2 += v[6] * v[6]; s3 += v[7] * v[7];
        uint32_t hw_[4];
        #pragma unroll
        for (int i = 0; i < 4; i++) {
            __nv_bfloat16 h0 = __float2bfloat16(v[2 * i]);
            __nv_bfloat16 h1 = __float2bfloat16(v[2 * i + 1]);
            hw_[i] = (uint32_t)__bfloat16_as_ushort(h0) | ((uint32_t)__bfloat16_as_ushort(h1) << 16);
        }
        dhi[c >> 3] = make_uint4(hw_[0], hw_[1], hw_[2], hw_[3]);
    }
    g_xsq[p] = (s0 + s1) + (s2 + s3);
}

// ---------------- fused HMMA GEMM + top-2 argmin ----------------
#define SM_X   0
#define SM_W   65536
#define SM_RED 196608
#define SM_TOT (196608 + 6144)

__device__ __forceinline__ void stage_wtile(uint32_t sb, int ct, int tid) {
    int r = tid >> 1, half = tid & 1;
    uint32_t dst = sb + SM_W + (uint32_t)(ct & 1) * 65536 + (uint32_t)r * 512;
    uint32_t xm = (r & 7) << 4;
    const char* srow = (const char*)(g_whi + (size_t)(ct * 128 + r) * CDIM);
    #pragma unroll
    for (int j = 0; j < 16; j++) {
        uint32_t kb = half * 256 + j * 16;
        cpasync16(dst + (kb ^ xm), srow + kb);
    }
}

__global__ __launch_bounds__(256, 1) void vq_mma() {
    extern __shared__ char smem[];
    uint32_t sb = smem_u32(smem);
    const int tid = threadIdx.x, l = tid & 31, wid = tid >> 5;
    const int mw = wid & 3, nw = wid >> 2;
    const int row0 = blockIdx.x * 128;
    float* s1sh = (float*)(smem + SM_RED);
    int*   i1sh = (int*)(smem + SM_RED + 2048);
    float* s2sh = (float*)(smem + SM_RED + 4096);

    {
        int r = tid >> 1, half = tid & 1;
        const char* shi = (const char*)(g_xhi + (size_t)(row0 + r) * CDIM);
        uint32_t dx = sb + SM_X + (uint32_t)r * 512;
        uint32_t xm = (r & 7) << 4;
        #pragma unroll
        for (int j = 0; j < 16; j++) {
            uint32_t kb = half * 256 + j * 16;
            cpasync16(dx + (kb ^ xm), shi + kb);
        }
    }
    stage_wtile(sb, 0, tid);
    asm volatile("cp.async.commit_group;" ::: "memory");
    stage_wtile(sb, 1, tid);
    asm volatile("cp.async.commit_group;" ::: "memory");

    float xsqr[16];
    #pragma unroll
    for (int s = 0; s < 16; s++) {
        int px = nw * 64 + (s >> 1) * 8 + (l & 3) * 2 + (s & 1);
        xsqr[s] = g_xsq[row0 + px];
    }

    uint32_t a_row[2], a_x[2];
    #pragma unroll
    for (int tm = 0; tm < 2; tm++) {
        int rA = mw * 32 + tm * 16 + (l & 15);
        a_row[tm] = rA * 512;
        a_x[tm] = (rA & 7) << 4;
    }
    const uint32_t off16a = (l >> 4) * 16;
    uint32_t b_row[4], b_x[4];
    #pragma unroll
    for (int tp = 0; tp < 4; tp++) {
        int rB = nw * 64 + tp * 16 + (l & 7) + ((l >> 4) << 3);
        b_row[tp] = rB * 512;
        b_x[tp] = (rB & 7) << 4;
    }
    const uint32_t off16b = ((l >> 3) & 1) * 16;

    float acc[2][8][4];
    #pragma unroll
    for (int i = 0; i < 2; i++)
        #pragma unroll
        for (int j = 0; j < 8; j++)
            #pragma unroll
            for (int k = 0; k < 4; k++) acc[i][j][k] = 0.f;

    float best_s[16], sec_s[16];
    int best_i[16];
    #pragma unroll
    for (int s = 0; s < 16; s++) { best_s[s] = 3.4e38f; sec_s[s] = 3.4e38f; best_i[s] = 0; }

    for (int ct = 0; ct < 8; ct++) {
        if (ct < 7) asm volatile("cp.async.wait_group 1;" ::: "memory");
        else        asm volatile("cp.async.wait_group 0;" ::: "memory");
        __syncthreads();

        uint32_t bufw = sb + SM_W + (uint32_t)(ct & 1) * 65536;
        #pragma unroll 4
        for (int kk = 0; kk < 16; kk++) {
            uint32_t a0[4], a1[4];
            uint32_t ca = kk * 32 + off16a;
            ldsm4(a0, bufw + a_row[0] + (ca ^ a_x[0]));
            ldsm4(a1, bufw + a_row[1] + (ca ^ a_x[1]));
            uint32_t kb = kk * 32 + off16b;
            #pragma unroll
            for (int tp = 0; tp < 4; tp++) {
                uint32_t b[4];
                ldsm4(b, sb + SM_X + b_row[tp] + (kb ^ b_x[tp]));
                mma_bf16(acc[0][2 * tp],     a0, b);
                mma_bf16(acc[0][2 * tp + 1], a0, b + 2);
                mma_bf16(acc[1][2 * tp],     a1, b);
                mma_bf16(acc[1][2 * tp + 1], a1, b + 2);
            }
        }
        __syncthreads();
        if (ct + 2 < 8) {
            stage_wtile(sb, ct + 2, tid);
            asm volatile("cp.async.commit_group;" ::: "memory");
        }

        {
            int cb = ct * 128 + mw * 32 + (l >> 2);
            float wq0 = __ldg(&g_wsq[cb]);
            float wq1 = __ldg(&g_wsq[cb + 8]);
            float wq2 = __ldg(&g_wsq[cb + 16]);
            float wq3 = __ldg(&g_wsq[cb + 24]);
            #pragma unroll
            for (int tm = 0; tm < 2; tm++) {
                float wlo_ = tm ? wq2 : wq0;
                float whi_ = tm ? wq3 : wq1;
                int c_lo = cb + tm * 16, c_hi = cb + tm * 16 + 8;
                #pragma unroll
                for (int tn = 0; tn < 8; tn++) {
                    #pragma unroll
                    for (int rg = 0; rg < 4; rg++) {
                        int slot = tn * 2 + (rg & 1);
                        float dot = acc[tm][tn][rg];
                        float wq = (rg >> 1) ? whi_ : wlo_;
                        int code = (rg >> 1) ? c_hi : c_lo;
                        float s = __fadd_rn(__fsub_rn(xsqr[slot],
                                                      __fmul_rn(2.0f, dot)), wq);
                        if (s < best_s[slot]) {
                            sec_s[slot] = best_s[slot];
                            best_s[slot] = s; best_i[slot] = code;
                        } else if (s < sec_s[slot]) {
                            sec_s[slot] = s;
                        }
                        acc[tm][tn][rg] = 0.f;
                    }
                }
            }
        }
    }

    #pragma unroll
    for (int s = 0; s < 16; s++) {
        float bs = best_s[s], ss = sec_s[s];
        int bi = best_i[s];
        #pragma unroll
        for (int off = 4; off <= 16; off <<= 1) {
            float ob = __shfl_xor_sync(0xffffffffu, bs, off);
            int   oi = __shfl_xor_sync(0xffffffffu, bi, off);
            float os = __shfl_xor_sync(0xffffffffu, ss, off);
            bool take = (ob < bs) || (ob == bs && oi < bi);
            float losing = take ? bs : ob;
            if (take) { bs = ob; bi = oi; }
            ss = fminf(fminf(ss, os), losing);
        }
        if ((l >> 2) == 0) {
            int px = nw * 64 + (s >> 1) * 8 + (l & 3) * 2 + (s & 1);
            s1sh[mw * 128 + px] = bs;
            i1sh[mw * 128 + px] = bi;
            s2sh[mw * 128 + px] = ss;
        }
    }
    __syncthreads();

    if (tid < 128) {
        float bs = s1sh[tid]; int bi = i1sh[tid]; float ss = s2sh[tid];
        #pragma unroll
        for (int wv = 1; wv < 4; wv++) {
            float ob = s1sh[wv * 128 + tid];
            int   oi = i1sh[wv * 128 + tid];
            float os = s2sh[wv * 128 + tid];
            bool take = (ob < bs) || (ob == bs && oi < bi);
            float losing = take ? bs : ob;
            if (take) { bs = ob; bi = oi; }
            ss = fminf(fminf(ss, os), losing);
        }
        g_idx[row0 + tid] = bi;
        g_bests[row0 + tid] = bs;
        if (ss - bs < GAP_THRESH) {
            g_key[row0 + tid] = ~0ull;
            int slot = atomicAdd(&g_flag_cnt, 1);
            if (slot < FLAG_CAP) g_flag_list[slot] = row0 + tid;
        }
    }
}

// ---------------- rescue scan: approx-rescore flagged px, emit candidates ----------------
// smem: XS 64KB | W 2x64KB | pxid 512B
#define SC_PX  196608
#define SC_TOT (196608 + 512)

__global__ __launch_bounds__(256, 1) void rescue_scan() {
    extern __shared__ char smem[];
    uint32_t sb = smem_u32(smem);
    const int tid = threadIdx.x, l = tid & 31, wid = tid >> 5;
    const int mw = wid & 3, nw = wid >> 2;
    const int split = blockIdx.x & 3;        // code quarter
    const int gslot = blockIdx.x >> 2;       // group slot (64)
    int* pxid = (int*)(smem + SC_PX);

    int nflag = g_flag_cnt;
    if (nflag > FLAG_CAP) nflag = FLAG_CAP;
    int ngroups = (nflag + 127) >> 7;
    if (gslot >= ngroups) return;

    // Stage this split's two W tiles once (persist across groups)
    stage_wtile(sb, split * 2, tid);
    stage_wtile(sb, split * 2 + 1, tid);
    asm volatile("cp.async.commit_group;" ::: "memory");

    uint32_t a_row[2], a_x[2];
    #pragma unroll
    for (int tm = 0; tm < 2; tm++) {
        int rA = mw * 32 + tm * 16 + (l & 15);
        a_row[tm] = rA * 512;
        a_x[tm] = (rA & 7) << 4;
    }
    const uint32_t off16a = (l >> 4) * 16;
    uint32_t b_row[4], b_x[4];
    #pragma unroll
    for (int tp = 0; tp < 4; tp++) {
        int rB = nw * 64 + tp * 16 + (l & 7) + ((l >> 4) << 3);
        b_row[tp] = rB * 512;
        b_x[tp] = (rB & 7) << 4;
    }
    const uint32_t off16b = ((l >> 3) & 1) * 16;

    float acc[2][8][4];
    #pragma unroll
    for (int i = 0; i < 2; i++)
        #pragma unroll
        for (int j = 0; j < 8; j++)
            #pragma unroll
            for (int k = 0; k < 4; k++) acc[i][j][k] = 0.f;

    for (int grp = gslot; grp < ngroups; grp += 64) {
        int base = grp * 128;
        __syncthreads();     // previous group done with XS
        if (tid < 128) {
            int fi = base + tid;
            pxid[tid] = g_flag_list[(fi < nflag) ? fi : (nflag - 1)];
        }
        __syncthreads();

        // Gather flagged pixels' bf16 rows into XS (same swizzle as vq_mma)
        {
            int r = tid >> 1, half = tid & 1;
            const char* shi = (const char*)(g_xhi + (size_t)pxid[r] * CDIM);
            uint32_t dx = sb + SM_X + (uint32_t)r * 512;
            uint32_t xm = (r & 7) << 4;
            #pragma unroll
            for (int j = 0; j < 16; j++) {
                uint32_t kb = half * 256 + j * 16;
                cpasync16(dx + (kb ^ xm), shi + kb);
            }
        }
        asm volatile("cp.async.commit_group;" ::: "memory");

        // per-slot pixel info
        float xsqr[16], lims[16];
        int pxs[16];
        #pragma unroll
        for (int s = 0; s < 16; s++) {
            int r = nw * 64 + (s >> 1) * 8 + (l & 3) * 2 + (s & 1);
            int p = pxid[r];
            pxs[s] = p;
            xsqr[s] = g_xsq[p];
            lims[s] = g_bests[p] + GAP_THRESH;
        }

        asm volatile("cp.async.wait_group 0;" ::: "memory");
        __syncthreads();

        #pragma unroll
        for (int ct2 = 0; ct2 < 2; ct2++) {
            int ct = split * 2 + ct2;
            uint32_t bufw = sb + SM_W + (uint32_t)(ct & 1) * 65536;
            #pragma unroll 4
            for (int kk = 0; kk < 16; kk++) {
                uint32_t a0[4], a1[4];
                uint32_t ca = kk * 32 + off16a;
                ldsm4(a0, bufw + a_row[0] + (ca ^ a_x[0]));
                ldsm4(a1, bufw + a_row[1] + (ca ^ a_x[1]));
                uint32_t kb = kk * 32 + off16b;
                #pragma unroll
                for (int tp = 0; tp < 4; tp++) {
                    uint32_t b[4];
                    ldsm4(b, sb + SM_X + b_row[tp] + (kb ^ b_x[tp]));
                    mma_bf16(acc[0][2 * tp],     a0, b);
                    mma_bf16(acc[0][2 * tp + 1], a0, b + 2);
                    mma_bf16(acc[1][2 * tp],     a1, b);
                    mma_bf16(acc[1][2 * tp + 1], a1, b + 2);
                }
            }

            int cb = ct * 128 + mw * 32 + (l >> 2);
            float wq0 = __ldg(&g_wsq[cb]);
            float wq1 = __ldg(&g_wsq[cb + 8]);
            float wq2 = __ldg(&g_wsq[cb + 16]);
            float wq3 = __ldg(&g_wsq[cb + 24]);
            #pragma unroll
            for (int tm = 0; tm < 2; tm++) {
                float wlo_ = tm ? wq2 : wq0;
                float whi_ = tm ? wq3 : wq1;
                int c_lo = cb + tm * 16, c_hi = cb + tm * 16 + 8;
                #pragma unroll
                for (int tn = 0; tn < 8; tn++) {
                    #pragma unroll
                    for (int rg = 0; rg < 4; rg++) {
                        int slot = tn * 2 + (rg & 1);
                        float dot = acc[tm][tn][rg];
                        float wq = (rg >> 1) ? whi_ : wlo_;
                        int code = (rg >> 1) ? c_hi : c_lo;
                        float s = __fadd_rn(__fsub_rn(xsqr[slot],
                                                      __fmul_rn(2.0f, dot)), wq);
                        if (s < lims[slot]) {
                            int ci = atomicAdd(&g_cand_cnt, 1);
                            if (ci < CAND_CAP)
                                g_cand[ci] = ((unsigned)pxs[slot] << 16) | (unsigned)code;
                        }
                        acc[tm][tn][rg] = 0.f;
                    }
                }
            }
        }
    }
}

// ---------------- exact fp32 scoring of candidates (1 warp each) ----------------
__global__ __launch_bounds__(256) void rescue_exact(const float* __restrict__ x,
                                                    const float* __restrict__ w) {
    const int l = threadIdx.x & 31, wid = threadIdx.x >> 5;
    int total = g_cand_cnt;
    if (total > CAND_CAP) total = CAND_CAP;
    for (int ci = blockIdx.x * 8 + wid; ci < total; ci += gridDim.x * 8) {
        unsigned pc = g_cand[ci];
        int px = pc >> 16, code = pc & 0xFFFF;
        const float* xb = x + (size_t)(px >> 10) * (CDIM * HW) + (px & 1023);
        const float* wr = w + (size_t)code * CDIM;
        float dot = 0.f;
        #pragma unroll
        for (int j = 0; j < 8; j++) {
            int c = l + j * 32;
            dot = fmaf(__ldg(&xb[(size_t)c * HW]), __ldg(&wr[c]), dot);
        }
        #pragma unroll
        for (int o = 16; o > 0; o >>= 1) dot += __shfl_down_sync(0xffffffffu, dot, o);
        if (l == 0) {
            float s = __fadd_rn(__fsub_rn(g_xsq[px], __fmul_rn(2.0f, dot)),
                                __ldg(&g_wsq[code]));
            atomicMin(&g_key[px], packKey(s, (unsigned)code));
        }
    }
}

__global__ void rescue_apply() {
    int nflag = g_flag_cnt;
    if (nflag > FLAG_CAP) nflag = FLAG_CAP;
    for (int i = blockIdx.x * blockDim.x + threadIdx.x; i < nflag;
         i += gridDim.x * blockDim.x) {
        int p = g_flag_list[i];
        g_idx[p] = (int)(g_key[p] & 0xFFFFFFFFULL);
    }
}

// ---------------- gather + write outputs ----------------
__global__ __launch_bounds__(256) void gather_kernel(const float* __restrict__ w,
                                                     float* __restrict__ out) {
    __shared__ float wsh[32][257];
    __shared__ int idxsh[32];

    const int bh = blockIdx.x;
    const int b  = bh >> 5;
    const int h  = bh & 31;
    const int p0 = bh * 32;
    const int tid = threadIdx.x;

    if (tid < 32) {
        int idx = g_idx[p0 + tid];
        idxsh[tid] = idx;
        out[2 * BCHW + p0 + tid] = (float)idx;
    }
    __syncthreads();

    for (int j = tid; j < 32 * CDIM; j += 256) {
        int wl = j >> 8, c = j & 255;
        wsh[wl][c] = w[(size_t)idxsh[wl] * CDIM + c];
    }
    __syncthreads();

    const int qbase = b * (CDIM * HW) + h * 32;
    for (int j = tid; j < 32 * CDIM; j += 256) {
        int c = j >> 5, ww = j & 31;
        float v = wsh[ww][c];
        int addr = qbase + c * HW + ww;
        out[addr] = v;
        out[addr + BCHW] = v;
    }
}

extern "C" void kernel_launch(void* const* d_in, const int* in_sizes, int n_in,
                              void* d_out, int out_size) {
    const float* x = (const float*)d_in[0];   // (64, 256, 32, 32) f32
    const float* w = (const float*)d_in[1];   // (1024, 256) f32
    float* out = (float*)d_out;

    cudaFuncSetAttribute(vq_mma, cudaFuncAttributeMaxDynamicSharedMemorySize, SM_TOT);
    cudaFuncSetAttribute(rescue_scan, cudaFuncAttributeMaxDynamicSharedMemorySize, SC_TOT);

    prep_w<<<NCODE, 256>>>(w);
    prep_x<<<NPIX / 256, 256>>>(x);
    vq_mma<<<512, 256, SM_TOT>>>();
    rescue_scan<<<256, 256, SC_TOT>>>();
    rescue_exact<<<256, 256>>>(x, w);
    rescue_apply<<<64, 256>>>();
    gather_kernel<<<NPIX / 32, 256>>>(w, out);
}

// round 8
// speedup vs baseline: 1.9676x; 1.0132x over previous
#include <cuda_runtime.h>
#include <cuda_bf16.h>
#include <stdint.h>

#define NCODE 1024
#define CDIM  256
#define NPIX  65536
#define HW    1024
#define BCHW  16777216
#define FLAG_CAP 32768
#define CAND_CAP 131072
#define GAP_THRESH 6.0e-4f

// ---------------- device scratch (no allocations allowed) ----------------
__device__ __nv_bfloat16 g_xhi[(size_t)NPIX * CDIM];   // 32 MB
__device__ __nv_bfloat16 g_whi[NCODE * CDIM];
__device__ float g_wsq[NCODE];
__device__ float g_xsq[NPIX];
__device__ float g_bests[NPIX];
__device__ int   g_idx[NPIX];
__device__ unsigned long long g_key[NPIX];
__device__ int   g_flag_cnt;
__device__ int   g_flag_list[FLAG_CAP];
__device__ int   g_cand_cnt;
__device__ unsigned g_cand[CAND_CAP];

__device__ __forceinline__ uint32_t smem_u32(const void* p) {
    uint32_t a;
    asm("{ .reg .u64 t; cvta.to.shared.u64 t, %1; cvt.u32.u64 %0, t; }" : "=r"(a) : "l"(p));
    return a;
}

__device__ __forceinline__ unsigned long long packKey(float s, unsigned idx) {
    unsigned u = __float_as_uint(s);
    u = (u & 0x80000000u) ? ~u : (u | 0x80000000u);
    return (((unsigned long long)u) << 32) | (unsigned long long)idx;
}

__device__ __forceinline__ void cpasync16(uint32_t d, const void* s) {
    asm volatile("cp.async.ca.shared.global [%0], [%1], 16;" :: "r"(d), "l"(s) : "memory");
}

__device__ __forceinline__ void ldsm4(uint32_t* r, uint32_t addr) {
    asm volatile("ldmatrix.sync.aligned.m8n8.x4.shared.b16 {%0,%1,%2,%3}, [%4];"
                 : "=r"(r[0]), "=r"(r[1]), "=r"(r[2]), "=r"(r[3]) : "r"(addr));
}

__device__ __forceinline__ void mma_bf16(float* c, const uint32_t* a, const uint32_t* b) {
    asm volatile(
        "mma.sync.aligned.m16n8k16.row.col.f32.bf16.bf16.f32 "
        "{%0,%1,%2,%3}, {%4,%5,%6,%7}, {%8,%9}, {%0,%1,%2,%3};"
        : "+f"(c[0]), "+f"(c[1]), "+f"(c[2]), "+f"(c[3])
        : "r"(a[0]), "r"(a[1]), "r"(a[2]), "r"(a[3]), "r"(b[0]), "r"(b[1]));
}

// ---------------- prep kernels ----------------
__global__ void prep_w(const float* __restrict__ w) {
    __shared__ float red[8];
    int code = blockIdx.x, t = threadIdx.x;
    if (code == 0 && t == 0) { g_flag_cnt = 0; g_cand_cnt = 0; }
    float v = w[code * CDIM + t];
    g_whi[code * CDIM + t] = __float2bfloat16(v);
    float s = v * v;
    #pragma unroll
    for (int o = 16; o > 0; o >>= 1) s += __shfl_down_sync(0xffffffffu, s, o);
    if ((t & 31) == 0) red[t >> 5] = s;
    __syncthreads();
    if (t == 0) {
        g_wsq[code] = ((red[0] + red[1]) + (red[2] + red[3])) +
                      ((red[4] + red[5]) + (red[6] + red[7]));
    }
}

// x (B,C,H,W) f32 -> (pixel, C) bf16 + |x|^2
__global__ void prep_x(const float* __restrict__ x) {
    int p = blockIdx.x * 256 + threadIdx.x;
    const float* base = x + (size_t)(p >> 10) * (CDIM * HW) + (p & 1023);
    float s0 = 0.f, s1 = 0.f, s2 = 0.f, s3 = 0.f;
    uint4* dhi = (uint4*)(g_xhi + (size_t)p * CDIM);
    #pragma unroll 4
    for (int c = 0; c < CDIM; c += 8) {
        float v[8];
        #pragma unroll
        for (int i = 0; i < 8; i++) v[i] = base[(c + i) * HW];
        s0 += v[0] * v[0]; s1 += v[1] * v[1]; s2 += v[2] * v[2]; s3 += v[3] * v[3];
        s0 += v[4] * v[4]; s1 += v[5] * v[5]; s2 += v[6] * v[6]; s3 += v[7] * v[7];
        uint32_t hw_[4];
        #pragma unroll
        for (int i = 0; i < 4; i++) {
            __nv_bfloat16 h0 = __float2bfloat16(v[2 * i]);
            __nv_bfloat16 h1 = __float2bfloat16(v[2 * i + 1]);
            hw_[i] = (uint32_t)__bfloat16_as_ushort(h0) | ((uint32_t)__bfloat16_as_ushort(h1) << 16);
        }
        dhi[c >> 3] = make_uint4(hw_[0], hw_[1], hw_[2], hw_[3]);
    }
    g_xsq[p] = (s0 + s1) + (s2 + s3);
}

// ---------------- shared smem layout for vq_mma / rescue_scan ----------------
#define SM_X   0
#define SM_W   65536
#define SM_RED 196608
#define SM_TOT (196608 + 6144)

// 256-thread stager (used by rescue_scan)
__device__ __forceinline__ void stage_wtile(uint32_t sb, int ct, int tid) {
    int r = tid >> 1, half = tid & 1;
    uint32_t dst = sb + SM_W + (uint32_t)(ct & 1) * 65536 + (uint32_t)r * 512;
    uint32_t xm = (r & 7) << 4;
    const char* srow = (const char*)(g_whi + (size_t)(ct * 128 + r) * CDIM);
    #pragma unroll
    for (int j = 0; j < 16; j++) {
        uint32_t kb = half * 256 + j * 16;
        cpasync16(dst + (kb ^ xm), srow + kb);
    }
}

// 512-thread stager (used by vq_mma)
__device__ __forceinline__ void stage_wtile512(uint32_t sb, int ct, int tid) {
    int r = tid >> 2, q = tid & 3;
    uint32_t dst = sb + SM_W + (uint32_t)(ct & 1) * 65536 + (uint32_t)r * 512;
    uint32_t xm = (r & 7) << 4;
    const char* srow = (const char*)(g_whi + (size_t)(ct * 128 + r) * CDIM);
    #pragma unroll
    for (int j = 0; j < 8; j++) {
        uint32_t kb = q * 128 + j * 16;
        cpasync16(dst + (kb ^ xm), srow + kb);
    }
}

// ---------------- fused HMMA GEMM + top-2 argmin (512 threads, 16 warps) ----------------
__global__ __launch_bounds__(512, 1) void vq_mma() {
    extern __shared__ char smem[];
    uint32_t sb = smem_u32(smem);
    const int tid = threadIdx.x, l = tid & 31, wid = tid >> 5;
    const int mw = wid & 3;        // code-warp: 4 x 32 codes
    const int nw = wid >> 2;       // pixel-warp: 4 x 32 pixels
    const int row0 = blockIdx.x * 128;
    float* s1sh = (float*)(smem + SM_RED);
    int*   i1sh = (int*)(smem + SM_RED + 2048);
    float* s2sh = (float*)(smem + SM_RED + 4096);

    // Stage resident X strip (512B swizzled rows)
    {
        int r = tid >> 2, q = tid & 3;
        const char* shi = (const char*)(g_xhi + (size_t)(row0 + r) * CDIM);
        uint32_t dx = sb + SM_X + (uint32_t)r * 512;
        uint32_t xm = (r & 7) << 4;
        #pragma unroll
        for (int j = 0; j < 8; j++) {
            uint32_t kb = q * 128 + j * 16;
            cpasync16(dx + (kb ^ xm), shi + kb);
        }
    }
    stage_wtile512(sb, 0, tid);
    asm volatile("cp.async.commit_group;" ::: "memory");
    stage_wtile512(sb, 1, tid);
    asm volatile("cp.async.commit_group;" ::: "memory");

    // 8 pixel slots per lane: px = nw*32 + (s>>1)*8 + (l&3)*2 + (s&1)
    float xsqr[8];
    #pragma unroll
    for (int s = 0; s < 8; s++) {
        int px = nw * 32 + (s >> 1) * 8 + (l & 3) * 2 + (s & 1);
        xsqr[s] = g_xsq[row0 + px];
    }

    uint32_t a_row[2], a_x[2];
    #pragma unroll
    for (int tm = 0; tm < 2; tm++) {
        int rA = mw * 32 + tm * 16 + (l & 15);
        a_row[tm] = rA * 512;
        a_x[tm] = (rA & 7) << 4;
    }
    const uint32_t off16a = (l >> 4) * 16;
    uint32_t b_row[2], b_x[2];
    #pragma unroll
    for (int tp = 0; tp < 2; tp++) {
        int rB = nw * 32 + tp * 16 + (l & 7) + ((l >> 4) << 3);
        b_row[tp] = rB * 512;
        b_x[tp] = (rB & 7) << 4;
    }
    const uint32_t off16b = ((l >> 3) & 1) * 16;

    float acc[2][4][4];
    #pragma unroll
    for (int i = 0; i < 2; i++)
        #pragma unroll
        for (int j = 0; j < 4; j++)
            #pragma unroll
            for (int k = 0; k < 4; k++) acc[i][j][k] = 0.f;

    float best_s[8], sec_s[8];
    int best_i[8];
    #pragma unroll
    for (int s = 0; s < 8; s++) { best_s[s] = 3.4e38f; sec_s[s] = 3.4e38f; best_i[s] = 0; }

    for (int ct = 0; ct < 8; ct++) {
        if (ct < 7) asm volatile("cp.async.wait_group 1;" ::: "memory");
        else        asm volatile("cp.async.wait_group 0;" ::: "memory");
        __syncthreads();

        uint32_t bufw = sb + SM_W + (uint32_t)(ct & 1) * 65536;
        #pragma unroll 4
        for (int kk = 0; kk < 16; kk++) {
            uint32_t a0[4], a1[4];
            uint32_t ca = kk * 32 + off16a;
            ldsm4(a0, bufw + a_row[0] + (ca ^ a_x[0]));
            ldsm4(a1, bufw + a_row[1] + (ca ^ a_x[1]));
            uint32_t kb = kk * 32 + off16b;
            #pragma unroll
            for (int tp = 0; tp < 2; tp++) {
                uint32_t b[4];
                ldsm4(b, sb + SM_X + b_row[tp] + (kb ^ b_x[tp]));
                mma_bf16(acc[0][2 * tp],     a0, b);
                mma_bf16(acc[0][2 * tp + 1], a0, b + 2);
                mma_bf16(acc[1][2 * tp],     a1, b);
                mma_bf16(acc[1][2 * tp + 1], a1, b + 2);
            }
        }
        __syncthreads();   // all warps done reading bufw before restage
        if (ct + 2 < 8) {
            stage_wtile512(sb, ct + 2, tid);
            asm volatile("cp.async.commit_group;" ::: "memory");
        }

        // Fold this code tile into running top-2 (overlaps the async restage)
        {
            int cb = ct * 128 + mw * 32 + (l >> 2);
            float wq0 = __ldg(&g_wsq[cb]);
            float wq1 = __ldg(&g_wsq[cb + 8]);
            float wq2 = __ldg(&g_wsq[cb + 16]);
            float wq3 = __ldg(&g_wsq[cb + 24]);
            #pragma unroll
            for (int tm = 0; tm < 2; tm++) {
                float wlo_ = tm ? wq2 : wq0;
                float whi_ = tm ? wq3 : wq1;
                int c_lo = cb + tm * 16, c_hi = cb + tm * 16 + 8;
                #pragma unroll
                for (int tn = 0; tn < 4; tn++) {
                    #pragma unroll
                    for (int rg = 0; rg < 4; rg++) {
                        int slot = tn * 2 + (rg & 1);
                        float dot = acc[tm][tn][rg];
                        float wq = (rg >> 1) ? whi_ : wlo_;
                        int code = (rg >> 1) ? c_hi : c_lo;
                        float s = __fadd_rn(__fsub_rn(xsqr[slot],
                                                      __fmul_rn(2.0f, dot)), wq);
                        if (s < best_s[slot]) {
                            sec_s[slot] = best_s[slot];
                            best_s[slot] = s; best_i[slot] = code;
                        } else if (s < sec_s[slot]) {
                            sec_s[slot] = s;
                        }
                        acc[tm][tn][rg] = 0.f;
                    }
                }
            }
        }
    }

    // Cross-lane top-2 merge (8 lanes per pixel column set)
    #pragma unroll
    for (int s = 0; s < 8; s++) {
        float bs = best_s[s], ss = sec_s[s];
        int bi = best_i[s];
        #pragma unroll
        for (int off = 4; off <= 16; off <<= 1) {
            float ob = __shfl_xor_sync(0xffffffffu, bs, off);
            int   oi = __shfl_xor_sync(0xffffffffu, bi, off);
            float os = __shfl_xor_sync(0xffffffffu, ss, off);
            bool take = (ob < bs) || (ob == bs && oi < bi);
            float losing = take ? bs : ob;
            if (take) { bs = ob; bi = oi; }
            ss = fminf(fminf(ss, os), losing);
        }
        if ((l >> 2) == 0) {
            int px = nw * 32 + (s >> 1) * 8 + (l & 3) * 2 + (s & 1);
            s1sh[mw * 128 + px] = bs;
            i1sh[mw * 128 + px] = bi;
            s2sh[mw * 128 + px] = ss;
        }
    }
    __syncthreads();

    // Cross-warp merge (4 code-warps per pixel); flag near-ties for rescue
    if (tid < 128) {
        float bs = s1sh[tid]; int bi = i1sh[tid]; float ss = s2sh[tid];
        #pragma unroll
        for (int wv = 1; wv < 4; wv++) {
            float ob = s1sh[wv * 128 + tid];
            int   oi = i1sh[wv * 128 + tid];
            float os = s2sh[wv * 128 + tid];
            bool take = (ob < bs) || (ob == bs && oi < bi);
            float losing = take ? bs : ob;
            if (take) { bs = ob; bi = oi; }
            ss = fminf(fminf(ss, os), losing);
        }
        g_idx[row0 + tid] = bi;
        g_bests[row0 + tid] = bs;
        if (ss - bs < GAP_THRESH) {
            g_key[row0 + tid] = ~0ull;
            int slot = atomicAdd(&g_flag_cnt, 1);
            if (slot < FLAG_CAP) g_flag_list[slot] = row0 + tid;
        }
    }
}

// ---------------- rescue scan: approx-rescore flagged px, emit candidates ----------------
#define SC_PX  196608
#define SC_TOT (196608 + 512)

__global__ __launch_bounds__(256, 1) void rescue_scan() {
    extern __shared__ char smem[];
    uint32_t sb = smem_u32(smem);
    const int tid = threadIdx.x, l = tid & 31, wid = tid >> 5;
    const int mw = wid & 3, nw = wid >> 2;
    const int split = blockIdx.x & 3;        // code quarter
    const int gslot = blockIdx.x >> 2;       // group slot (64)
    int* pxid = (int*)(smem + SC_PX);

    int nflag = g_flag_cnt;
    if (nflag > FLAG_CAP) nflag = FLAG_CAP;
    int ngroups = (nflag + 127) >> 7;
    if (gslot >= ngroups) return;

    stage_wtile(sb, split * 2, tid);
    stage_wtile(sb, split * 2 + 1, tid);
    asm volatile("cp.async.commit_group;" ::: "memory");

    uint32_t a_row[2], a_x[2];
    #pragma unroll
    for (int tm = 0; tm < 2; tm++) {
        int rA = mw * 32 + tm * 16 + (l & 15);
        a_row[tm] = rA * 512;
        a_x[tm] = (rA & 7) << 4;
    }
    const uint32_t off16a = (l >> 4) * 16;
    uint32_t b_row[4], b_x[4];
    #pragma unroll
    for (int tp = 0; tp < 4; tp++) {
        int rB = nw * 64 + tp * 16 + (l & 7) + ((l >> 4) << 3);
        b_row[tp] = rB * 512;
        b_x[tp] = (rB & 7) << 4;
    }
    const uint32_t off16b = ((l >> 3) & 1) * 16;

    float acc[2][8][4];
    #pragma unroll
    for (int i = 0; i < 2; i++)
        #pragma unroll
        for (int j = 0; j < 8; j++)
            #pragma unroll
            for (int k = 0; k < 4; k++) acc[i][j][k] = 0.f;

    for (int grp = gslot; grp < ngroups; grp += 64) {
        int base = grp * 128;
        __syncthreads();     // previous group done with XS
        if (tid < 128) {
            int fi = base + tid;
            pxid[tid] = g_flag_list[(fi < nflag) ? fi : (nflag - 1)];
        }
        __syncthreads();

        {
            int r = tid >> 1, half = tid & 1;
            const char* shi = (const char*)(g_xhi + (size_t)pxid[r] * CDIM);
            uint32_t dx = sb + SM_X + (uint32_t)r * 512;
            uint32_t xm = (r & 7) << 4;
            #pragma unroll
            for (int j = 0; j < 16; j++) {
                uint32_t kb = half * 256 + j * 16;
                cpasync16(dx + (kb ^ xm), shi + kb);
            }
        }
        asm volatile("cp.async.commit_group;" ::: "memory");

        float xsqr[16], lims[16];
        int pxs[16];
        #pragma unroll
        for (int s = 0; s < 16; s++) {
            int r = nw * 64 + (s >> 1) * 8 + (l & 3) * 2 + (s & 1);
            int p = pxid[r];
            pxs[s] = p;
            xsqr[s] = g_xsq[p];
            lims[s] = g_bests[p] + GAP_THRESH;
        }

        asm volatile("cp.async.wait_group 0;" ::: "memory");
        __syncthreads();

        #pragma unroll
        for (int ct2 = 0; ct2 < 2; ct2++) {
            int ct = split * 2 + ct2;
            uint32_t bufw = sb + SM_W + (uint32_t)(ct & 1) * 65536;
            #pragma unroll 4
            for (int kk = 0; kk < 16; kk++) {
                uint32_t a0[4], a1[4];
                uint32_t ca = kk * 32 + off16a;
                ldsm4(a0, bufw + a_row[0] + (ca ^ a_x[0]));
                ldsm4(a1, bufw + a_row[1] + (ca ^ a_x[1]));
                uint32_t kb = kk * 32 + off16b;
                #pragma unroll
                for (int tp = 0; tp < 4; tp++) {
                    uint32_t b[4];
                    ldsm4(b, sb + SM_X + b_row[tp] + (kb ^ b_x[tp]));
                    mma_bf16(acc[0][2 * tp],     a0, b);
                    mma_bf16(acc[0][2 * tp + 1], a0, b + 2);
                    mma_bf16(acc[1][2 * tp],     a1, b);
                    mma_bf16(acc[1][2 * tp + 1], a1, b + 2);
                }
            }

            int cb = ct * 128 + mw * 32 + (l >> 2);
            float wq0 = __ldg(&g_wsq[cb]);
            float wq1 = __ldg(&g_wsq[cb + 8]);
            float wq2 = __ldg(&g_wsq[cb + 16]);
            float wq3 = __ldg(&g_wsq[cb + 24]);
            #pragma unroll
            for (int tm = 0; tm < 2; tm++) {
                float wlo_ = tm ? wq2 : wq0;
                float whi_ = tm ? wq3 : wq1;
                int c_lo = cb + tm * 16, c_hi = cb + tm * 16 + 8;
                #pragma unroll
                for (int tn = 0; tn < 8; tn++) {
                    #pragma unroll
                    for (int rg = 0; rg < 4; rg++) {
                        int slot = tn * 2 + (rg & 1);
                        float dot = acc[tm][tn][rg];
                        float wq = (rg >> 1) ? whi_ : wlo_;
                        int code = (rg >> 1) ? c_hi : c_lo;
                        float s = __fadd_rn(__fsub_rn(xsqr[slot],
                                                      __fmul_rn(2.0f, dot)), wq);
                        if (s < lims[slot]) {
                            int ci = atomicAdd(&g_cand_cnt, 1);
                            if (ci < CAND_CAP)
                                g_cand[ci] = ((unsigned)pxs[slot] << 16) | (unsigned)code;
                        }
                        acc[tm][tn][rg] = 0.f;
                    }
                }
            }
        }
    }
}

// ---------------- exact fp32 scoring of candidates (1 warp each) ----------------
__global__ __launch_bounds__(256) void rescue_exact(const float* __restrict__ x,
                                                    const float* __restrict__ w) {
    const int l = threadIdx.x & 31, wid = threadIdx.x >> 5;
    int total = g_cand_cnt;
    if (total > CAND_CAP) total = CAND_CAP;
    for (int ci = blockIdx.x * 8 + wid; ci < total; ci += gridDim.x * 8) {
        unsigned pc = g_cand[ci];
        int px = pc >> 16, code = pc & 0xFFFF;
        const float* xb = x + (size_t)(px >> 10) * (CDIM * HW) + (px & 1023);
        const float* wr = w + (size_t)code * CDIM;
        float dot = 0.f;
        #pragma unroll
        for (int j = 0; j < 8; j++) {
            int c = l + j * 32;
            dot = fmaf(__ldg(&xb[(size_t)c * HW]), __ldg(&wr[c]), dot);
        }
        #pragma unroll
        for (int o = 16; o > 0; o >>= 1) dot += __shfl_down_sync(0xffffffffu, dot, o);
        if (l == 0) {
            float s = __fadd_rn(__fsub_rn(g_xsq[px], __fmul_rn(2.0f, dot)),
                                __ldg(&g_wsq[code]));
            atomicMin(&g_key[px], packKey(s, (unsigned)code));
        }
    }
}

__global__ void rescue_apply() {
    int nflag = g_flag_cnt;
    if (nflag > FLAG_CAP) nflag = FLAG_CAP;
    for (int i = blockIdx.x * blockDim.x + threadIdx.x; i < nflag;
         i += gridDim.x * blockDim.x) {
        int p = g_flag_list[i];
        g_idx[p] = (int)(g_key[p] & 0xFFFFFFFFULL);
    }
}

// ---------------- gather + write outputs ----------------
__global__ __launch_bounds__(256) void gather_kernel(const float* __restrict__ w,
                                                     float* __restrict__ out) {
    __shared__ float wsh[32][257];
    __shared__ int idxsh[32];

    const int bh = blockIdx.x;
    const int b  = bh >> 5;
    const int h  = bh & 31;
    const int p0 = bh * 32;
    const int tid = threadIdx.x;

    if (tid < 32) {
        int idx = g_idx[p0 + tid];
        idxsh[tid] = idx;
        out[2 * BCHW + p0 + tid] = (float)idx;
    }
    __syncthreads();

    for (int j = tid; j < 32 * CDIM; j += 256) {
        int wl = j >> 8, c = j & 255;
        wsh[wl][c] = w[(size_t)idxsh[wl] * CDIM + c];
    }
    __syncthreads();

    const int qbase = b * (CDIM * HW) + h * 32;
    for (int j = tid; j < 32 * CDIM; j += 256) {
        int c = j >> 5, ww = j & 31;
        float v = wsh[ww][c];
        int addr = qbase + c * HW + ww;
        out[addr] = v;
        out[addr + BCHW] = v;
    }
}

extern "C" void kernel_launch(void* const* d_in, const int* in_sizes, int n_in,
                              void* d_out, int out_size) {
    const float* x = (const float*)d_in[0];   // (64, 256, 32, 32) f32
    const float* w = (const float*)d_in[1];   // (1024, 256) f32
    float* out = (float*)d_out;

    cudaFuncSetAttribute(vq_mma, cudaFuncAttributeMaxDynamicSharedMemorySize, SM_TOT);
    cudaFuncSetAttribute(rescue_scan, cudaFuncAttributeMaxDynamicSharedMemorySize, SC_TOT);

    prep_w<<<NCODE, 256>>>(w);
    prep_x<<<NPIX / 256, 256>>>(x);
    vq_mma<<<512, 512, SM_TOT>>>();
    rescue_scan<<<256, 256, SC_TOT>>>();
    rescue_exact<<<256, 256>>>(x, w);
    rescue_apply<<<64, 256>>>();
    gather_kernel<<<NPIX / 32, 256>>>(w, out);
}